// round 10
// baseline (speedup 1.0000x reference)
#include <cuda_runtime.h>
#include <cuda_fp16.h>
#include <cstdint>

// BMM_S8T_S8N_F16T producer/consumer persistent kernel, occ 2:
//  296 CTAs (2/SM), 320 threads: warps 0-7 compute (16-row slab each:
//  IMMA cols 0..71 + dp4a cols 72..127), warps 8-9 load+pack the NEXT tile.
// out[b,m,n] = f32( fp16_round( alpha * sum_k a[b,m,k]*b[b,n,k] ) )

#define MDIM 1024
#define NDIM 1024
#define KDIM 128
#define NTILES 4096
#define NCTAS 296

#define ROWSTRIDE 36
#define NI_MMA 9
#define COL_DP 72
#define NI_DP 7

#define BAR_FULL0 1
#define BAR_FULL1 2
#define BAR_FREE0 3
#define BAR_FREE1 4
#define BAR_CNT   320

#define PACK4(v) __byte_perm(__byte_perm((v).x, (v).y, 0x0040), \
                             __byte_perm((v).z, (v).w, 0x0040), 0x5410)

#define BAR_SYNC(id)   asm volatile("bar.sync %0, %1;"   :: "r"(id), "r"(BAR_CNT) : "memory")
#define BAR_ARRIVE(id) asm volatile("bar.arrive %0, %1;" :: "r"(id), "r"(BAR_CNT) : "memory")

__global__ __launch_bounds__(320, 2)
void bmm_s8_pc2_kernel(const int* __restrict__ A,
                       const int* __restrict__ Bmat,
                       const float* __restrict__ alpha_p,
                       float* __restrict__ Out) {
    __shared__ uint32_t As[2][128 * ROWSTRIDE];
    __shared__ uint32_t Bs[2][128 * ROWSTRIDE];

    const int tid  = threadIdx.x;
    const int lane = tid & 31;
    const int wid  = tid >> 5;

    if (wid >= 8) {
        // ================== LOADER WARPS (64 threads) ==================
        const int ltid = tid - 256;          // 0..63
        int i = 0;
        for (int t = blockIdx.x; t < NTILES; t += NCTAS, i++) {
            const int b = i & 1;
            if (i >= 2) BAR_SYNC(BAR_FREE0 + b);

            const int bn = t & 7, bm = (t >> 3) & 7, bz = t >> 6;
            const int* Ab = A    + ((size_t)bz * MDIM + bm * 128) * KDIM;
            const int* Bb = Bmat + ((size_t)bz * NDIM + bn * 128) * KDIM;

            // Each operand: 4096 int4 loads -> 4096 packed words.
            // 64 lanes x 64 int4 per operand; 2-deep batch pipeline (4 int4/batch).
            #define LOAD_OP(SRC, DST) do {                                      \
                int4 q0[4], q1[4];                                              \
                _Pragma("unroll")                                               \
                for (int u = 0; u < 4; u++)                                     \
                    q0[u] = *(const int4*)((SRC) + (ltid + u * 64) * 4);        \
                _Pragma("unroll 4")                                             \
                for (int bt = 0; bt < 16; bt++) {                               \
                    int4* cur = (bt & 1) ? q1 : q0;                             \
                    int4* nxt = (bt & 1) ? q0 : q1;                             \
                    if (bt < 15) {                                              \
                        _Pragma("unroll")                                       \
                        for (int u = 0; u < 4; u++)                             \
                            nxt[u] = *(const int4*)((SRC) +                     \
                                      (ltid + ((bt + 1) * 4 + u) * 64) * 4);    \
                    }                                                           \
                    _Pragma("unroll")                                           \
                    for (int u = 0; u < 4; u++) {                               \
                        int i4  = ltid + (bt * 4 + u) * 64;                     \
                        int row = i4 >> 5, col = i4 & 31;                       \
                        (DST)[row * ROWSTRIDE + col] = PACK4(cur[u]);           \
                    }                                                           \
                }                                                               \
            } while (0)

            LOAD_OP(Ab, As[b]);
            LOAD_OP(Bb, Bs[b]);
            #undef LOAD_OP

            BAR_ARRIVE(BAR_FULL0 + b);
        }
        return;
    }

    // ================== COMPUTE WARPS (256 threads) ==================
    const int rb = wid * 16;
    const int lq = lane >> 2;
    const int lr = lane & 3;
    const int g  = lane >> 3;
    const int j  = lane & 7;
    const float alpha = *alpha_p;

    int i = 0;
    for (int t = blockIdx.x; t < NTILES; t += NCTAS, i++) {
        const int b = i & 1;
        BAR_SYNC(BAR_FULL0 + b);

        int macc[NI_MMA][4];
        #pragma unroll
        for (int ni = 0; ni < NI_MMA; ni++)
            #pragma unroll
            for (int r = 0; r < 4; r++) macc[ni][r] = 0;

        int dacc[4][NI_DP];
        #pragma unroll
        for (int mi = 0; mi < 4; mi++)
            #pragma unroll
            for (int ni = 0; ni < NI_DP; ni++) dacc[mi][ni] = 0;

        #pragma unroll
        for (int ks = 0; ks < 4; ks++) {
            // --- IMMA: cols 0..71 ---
            uint32_t af[4];
            {
                const uint32_t* p = &As[b][(rb + lq) * ROWSTRIDE + ks * 8 + lr];
                af[0] = p[0];  af[2] = p[4];
                const uint32_t* p8 = p + 8 * ROWSTRIDE;
                af[1] = p8[0]; af[3] = p8[4];
            }
            #pragma unroll
            for (int ni = 0; ni < NI_MMA; ni++) {
                const uint32_t* q = &Bs[b][(ni * 8 + lq) * ROWSTRIDE + ks * 8 + lr];
                uint32_t b0 = q[0], b1 = q[4];
                asm volatile(
                    "mma.sync.aligned.m16n8k32.row.col.s32.s8.s8.s32 "
                    "{%0,%1,%2,%3}, {%4,%5,%6,%7}, {%8,%9}, {%0,%1,%2,%3};"
                    : "+r"(macc[ni][0]), "+r"(macc[ni][1]),
                      "+r"(macc[ni][2]), "+r"(macc[ni][3])
                    : "r"(af[0]), "r"(af[1]), "r"(af[2]), "r"(af[3]),
                      "r"(b0), "r"(b1));
            }
            // --- dp4a: cols 72..127 ---
            #pragma unroll
            for (int c = 0; c < 2; c++) {
                const int kw = ks * 8 + c * 4;
                uint4 av[4];
                #pragma unroll
                for (int mi = 0; mi < 4; mi++)
                    av[mi] = *(const uint4*)&As[b][(rb + g + 4 * mi) * ROWSTRIDE + kw];
                #pragma unroll
                for (int ni = 0; ni < NI_DP; ni++) {
                    uint4 bv = *(const uint4*)&Bs[b][(COL_DP + j + 8 * ni) * ROWSTRIDE + kw];
                    #pragma unroll
                    for (int mi = 0; mi < 4; mi++) {
                        int v = dacc[mi][ni];
                        v = __dp4a((int)av[mi].x, (int)bv.x, v);
                        v = __dp4a((int)av[mi].y, (int)bv.y, v);
                        v = __dp4a((int)av[mi].z, (int)bv.z, v);
                        v = __dp4a((int)av[mi].w, (int)bv.w, v);
                        dacc[mi][ni] = v;
                    }
                }
            }
        }

        BAR_ARRIVE(BAR_FREE0 + b);   // smem reads done; loaders may refill

        // --- Epilogue (registers only) ---
        const int bn = t & 7, bm = (t >> 3) & 7, bz = t >> 6;
        float* obase = Out + ((size_t)bz * MDIM + bm * 128) * NDIM + bn * 128;

        #pragma unroll
        for (int ni = 0; ni < NI_MMA; ni++) {
            int c0 = ni * 8 + lr * 2;
            float2 v0;
            v0.x = __half2float(__float2half_rn(alpha * (float)macc[ni][0]));
            v0.y = __half2float(__float2half_rn(alpha * (float)macc[ni][1]));
            *(float2*)(obase + (size_t)(rb + lq) * NDIM + c0) = v0;
            float2 v1;
            v1.x = __half2float(__float2half_rn(alpha * (float)macc[ni][2]));
            v1.y = __half2float(__float2half_rn(alpha * (float)macc[ni][3]));
            *(float2*)(obase + (size_t)(rb + lq + 8) * NDIM + c0) = v1;
        }
        #pragma unroll
        for (int mi = 0; mi < 4; mi++) {
            float* orow = obase + (size_t)(rb + g + 4 * mi) * NDIM;
            #pragma unroll
            for (int ni = 0; ni < NI_DP; ni++) {
                int col = COL_DP + j + 8 * ni;
                orow[col] = __half2float(__float2half_rn(alpha * (float)dacc[mi][ni]));
            }
        }
    }
}

extern "C" void kernel_launch(void* const* d_in, const int* in_sizes, int n_in,
                              void* d_out, int out_size) {
    // alpha is the size-1 input; the two large tensors are a then b in index order.
    int ai = -1, bi = -1, si = -1;
    for (int i = 0; i < n_in; i++) {
        if (in_sizes[i] == 1) { si = i; }
        else if (ai < 0)      { ai = i; }
        else                  { bi = i; }
    }
    const int*   a     = (const int*)d_in[ai];
    const int*   b     = (const int*)d_in[bi];
    const float* alpha = (const float*)d_in[si];
    float*       out   = (float*)d_out;

    bmm_s8_pc2_kernel<<<NCTAS, 320>>>(a, b, alpha, out);
}

// round 11
// speedup vs baseline: 1.2770x; 1.2770x over previous
#include <cuda_runtime.h>
#include <cuda_fp16.h>
#include <cstdint>

// BMM_S8T_S8N_F16T hybrid, occupancy-3 variant:
// CTA tile 128(M) x 64(N), 256 threads; each warp owns a 16-row slab:
// IMMA covers cols 0..31, dp4a covers cols 32..63 (independent accumulators,
// interleaved per k-step so tensor + ALU pipes run concurrently).
// out[b,m,n] = f32( fp16_round( alpha * sum_k a[b,m,k]*b[b,n,k] ) )

#define BATCH 64
#define MDIM 1024
#define NDIM 1024
#define KDIM 128

#define BM 128
#define BN 64
#define ROWSTRIDE 36       // 32 k-words + 4 pad -> conflict-free banks

#define NI_MMA 4           // IMMA cols 0..31
#define COL_DP 32          // dp4a cols 32..63
#define NI_DP 4

#define PACK4(v) __byte_perm(__byte_perm((v).x, (v).y, 0x0040), \
                             __byte_perm((v).z, (v).w, 0x0040), 0x5410)

__global__ __launch_bounds__(256, 3)
void bmm_s8_occ3_kernel(const int* __restrict__ A,
                        const int* __restrict__ Bmat,
                        const float* __restrict__ alpha_p,
                        float* __restrict__ Out) {
    __shared__ uint32_t As[BM * ROWSTRIDE];   // 18 KB
    __shared__ uint32_t Bs[BN * ROWSTRIDE];   //  9 KB

    const int tid  = threadIdx.x;
    const int lane = tid & 31;
    const int wid  = tid >> 5;

    const int bn = blockIdx.x;   // N block (16)
    const int bm = blockIdx.y;   // M block (8)
    const int bz = blockIdx.z;   // batch  (64)

    const int* Abase = A    + ((size_t)bz * MDIM + (size_t)bm * BM) * KDIM;
    const int* Bbase = Bmat + ((size_t)bz * NDIM + (size_t)bn * BN) * KDIM;

    // ---- Load tiles: A 4096 words (16/thread), B 2048 words (8/thread) ----
    #pragma unroll
    for (int i = 0; i < 16; i++) {
        int idx = tid + i * 256;
        int row = idx >> 5, col = idx & 31;
        int4 va = *(const int4*)(Abase + row * KDIM + col * 4);
        As[row * ROWSTRIDE + col] = PACK4(va);
    }
    #pragma unroll
    for (int i = 0; i < 8; i++) {
        int idx = tid + i * 256;
        int row = idx >> 5, col = idx & 31;
        int4 vb = *(const int4*)(Bbase + row * KDIM + col * 4);
        Bs[row * ROWSTRIDE + col] = PACK4(vb);
    }
    __syncthreads();

    // ---- Warp slab: rows wid*16 .. +15 ----
    const int rb = wid * 16;
    const int lq = lane >> 2;    // mma group 0..7
    const int lr = lane & 3;     // mma thread-in-group
    const int g  = lane >> 3;    // dp4a row interleave 0..3
    const int j  = lane & 7;     // dp4a col interleave 0..7

    int macc[NI_MMA][4];
    #pragma unroll
    for (int ni = 0; ni < NI_MMA; ni++)
        #pragma unroll
        for (int r = 0; r < 4; r++) macc[ni][r] = 0;

    int dacc[4][NI_DP];
    #pragma unroll
    for (int mi = 0; mi < 4; mi++)
        #pragma unroll
        for (int ni = 0; ni < NI_DP; ni++) dacc[mi][ni] = 0;

    #pragma unroll
    for (int ks = 0; ks < 4; ks++) {
        // --- IMMA: cols 0..31 ---
        uint32_t af[4];
        {
            const uint32_t* p = &As[(rb + lq) * ROWSTRIDE + ks * 8 + lr];
            af[0] = p[0];  af[2] = p[4];
            const uint32_t* p8 = p + 8 * ROWSTRIDE;
            af[1] = p8[0]; af[3] = p8[4];
        }
        #pragma unroll
        for (int ni = 0; ni < NI_MMA; ni++) {
            const uint32_t* q = &Bs[(ni * 8 + lq) * ROWSTRIDE + ks * 8 + lr];
            uint32_t b0 = q[0], b1 = q[4];
            asm volatile(
                "mma.sync.aligned.m16n8k32.row.col.s32.s8.s8.s32 "
                "{%0,%1,%2,%3}, {%4,%5,%6,%7}, {%8,%9}, {%0,%1,%2,%3};"
                : "+r"(macc[ni][0]), "+r"(macc[ni][1]),
                  "+r"(macc[ni][2]), "+r"(macc[ni][3])
                : "r"(af[0]), "r"(af[1]), "r"(af[2]), "r"(af[3]),
                  "r"(b0), "r"(b1));
        }
        // --- dp4a: cols 32..63 ---
        #pragma unroll
        for (int c = 0; c < 2; c++) {
            const int kw = ks * 8 + c * 4;
            uint4 av[4];
            #pragma unroll
            for (int mi = 0; mi < 4; mi++)
                av[mi] = *(const uint4*)&As[(rb + g + 4 * mi) * ROWSTRIDE + kw];
            #pragma unroll
            for (int ni = 0; ni < NI_DP; ni++) {
                uint4 bv = *(const uint4*)&Bs[(COL_DP + j + 8 * ni) * ROWSTRIDE + kw];
                #pragma unroll
                for (int mi = 0; mi < 4; mi++) {
                    int v = dacc[mi][ni];
                    v = __dp4a((int)av[mi].x, (int)bv.x, v);
                    v = __dp4a((int)av[mi].y, (int)bv.y, v);
                    v = __dp4a((int)av[mi].z, (int)bv.z, v);
                    v = __dp4a((int)av[mi].w, (int)bv.w, v);
                    dacc[mi][ni] = v;
                }
            }
        }
    }

    // ---- Epilogue: round(alpha * acc) through fp16, store as f32 ----
    const float alpha = *alpha_p;
    float* obase = Out + ((size_t)bz * MDIM + (size_t)bm * BM) * NDIM + (size_t)bn * BN;

    // IMMA outputs: rows rb+lq (+8), cols ni*8 + lr*2 (+1)
    #pragma unroll
    for (int ni = 0; ni < NI_MMA; ni++) {
        int c0 = ni * 8 + lr * 2;
        float2 v0;
        v0.x = __half2float(__float2half_rn(alpha * (float)macc[ni][0]));
        v0.y = __half2float(__float2half_rn(alpha * (float)macc[ni][1]));
        *(float2*)(obase + (size_t)(rb + lq) * NDIM + c0) = v0;
        float2 v1;
        v1.x = __half2float(__float2half_rn(alpha * (float)macc[ni][2]));
        v1.y = __half2float(__float2half_rn(alpha * (float)macc[ni][3]));
        *(float2*)(obase + (size_t)(rb + lq + 8) * NDIM + c0) = v1;
    }
    // dp4a outputs: rows rb + g + 4*mi, cols COL_DP + j + 8*ni
    #pragma unroll
    for (int mi = 0; mi < 4; mi++) {
        float* orow = obase + (size_t)(rb + g + 4 * mi) * NDIM;
        #pragma unroll
        for (int ni = 0; ni < NI_DP; ni++) {
            int col = COL_DP + j + 8 * ni;
            orow[col] = __half2float(__float2half_rn(alpha * (float)dacc[mi][ni]));
        }
    }
}

extern "C" void kernel_launch(void* const* d_in, const int* in_sizes, int n_in,
                              void* d_out, int out_size) {
    // alpha is the size-1 input; the two large tensors are a then b in index order.
    int ai = -1, bi = -1, si = -1;
    for (int i = 0; i < n_in; i++) {
        if (in_sizes[i] == 1) { si = i; }
        else if (ai < 0)      { ai = i; }
        else                  { bi = i; }
    }
    const int*   a     = (const int*)d_in[ai];
    const int*   b     = (const int*)d_in[bi];
    const float* alpha = (const float*)d_in[si];
    float*       out   = (float*)d_out;

    dim3 grid(NDIM / BN, MDIM / BM, BATCH);   // (16, 8, 64) = 8192 CTAs
    dim3 block(256);
    bmm_s8_occ3_kernel<<<grid, block>>>(a, b, alpha, out);
}

// round 12
// speedup vs baseline: 1.3226x; 1.0357x over previous
#include <cuda_runtime.h>
#include <cuda_fp16.h>
#include <cstdint>

// BMM_S8T_S8N_F16T two-phase:
//  1) pack kernel: int32 inputs -> int8 packed scratch (static __device__)
//  2) main kernel: occ-3 hybrid (CTA tile 128x64; per 16-row warp slab:
//     IMMA cols 0..31, dp4a cols 32..63) loading packed uint4 tiles.
// out[b,m,n] = f32( fp16_round( alpha * sum_k a[b,m,k]*b[b,n,k] ) )

#define BATCH 64
#define MDIM 1024
#define NDIM 1024
#define KDIM 128

#define BM 128
#define BN 64
#define ROWSTRIDE 36       // 32 k-words + 4 pad -> conflict-free banks

#define NI_MMA 4           // IMMA cols 0..31
#define COL_DP 32          // dp4a cols 32..63
#define NI_DP 4

// Packed scratch: 8.39 MB per operand (rows x 128 bytes = 8 uint4 per row)
__device__ uint4 g_Apack[(size_t)BATCH * MDIM * 8];
__device__ uint4 g_Bpack[(size_t)BATCH * NDIM * 8];

#define PACK4(v) __byte_perm(__byte_perm((v).x, (v).y, 0x0040), \
                             __byte_perm((v).z, (v).w, 0x0040), 0x5410)

// ---------------- Pre-pass: pack int32 -> int8 ----------------
__global__ __launch_bounds__(256)
void pack_kernel(const int* __restrict__ A, const int* __restrict__ Bmat) {
    const int idx = blockIdx.x * 256 + threadIdx.x;   // one uint4 (16 int8) each
    const size_t base = (size_t)idx * 16;

    uint4 pa;
    {
        int4 v0 = *(const int4*)(A + base);
        int4 v1 = *(const int4*)(A + base + 4);
        int4 v2 = *(const int4*)(A + base + 8);
        int4 v3 = *(const int4*)(A + base + 12);
        pa.x = PACK4(v0); pa.y = PACK4(v1); pa.z = PACK4(v2); pa.w = PACK4(v3);
    }
    g_Apack[idx] = pa;

    uint4 pb;
    {
        int4 v0 = *(const int4*)(Bmat + base);
        int4 v1 = *(const int4*)(Bmat + base + 4);
        int4 v2 = *(const int4*)(Bmat + base + 8);
        int4 v3 = *(const int4*)(Bmat + base + 12);
        pb.x = PACK4(v0); pb.y = PACK4(v1); pb.z = PACK4(v2); pb.w = PACK4(v3);
    }
    g_Bpack[idx] = pb;
}

// ---------------- Main kernel: occ-3 hybrid on packed data ----------------
__global__ __launch_bounds__(256, 3)
void bmm_s8_main_kernel(const float* __restrict__ alpha_p,
                        float* __restrict__ Out) {
    __shared__ uint32_t As[BM * ROWSTRIDE];   // 18 KB
    __shared__ uint32_t Bs[BN * ROWSTRIDE];   //  9 KB

    const int tid  = threadIdx.x;
    const int lane = tid & 31;
    const int wid  = tid >> 5;

    const int bn = blockIdx.x;   // N block (16)
    const int bm = blockIdx.y;   // M block (8)
    const int bz = blockIdx.z;   // batch  (64)

    // ---- Load packed tiles: A 1024 uint4 (4/thread), B 512 uint4 (2/thread) ----
    {
        const uint4* Ab = g_Apack + ((size_t)bz * MDIM + bm * BM) * 8;
        #pragma unroll
        for (int i = 0; i < 4; i++) {
            int idx = tid + i * 256;          // 0..1023
            int row = idx >> 3, qg = idx & 7;
            uint4 v = Ab[row * 8 + qg];
            *(uint4*)&As[row * ROWSTRIDE + qg * 4] = v;
        }
        const uint4* Bb = g_Bpack + ((size_t)bz * NDIM + bn * BN) * 8;
        #pragma unroll
        for (int i = 0; i < 2; i++) {
            int idx = tid + i * 256;          // 0..511
            int row = idx >> 3, qg = idx & 7;
            uint4 v = Bb[row * 8 + qg];
            *(uint4*)&Bs[row * ROWSTRIDE + qg * 4] = v;
        }
    }
    __syncthreads();

    // ---- Warp slab: rows wid*16 .. +15 ----
    const int rb = wid * 16;
    const int lq = lane >> 2;    // mma group 0..7
    const int lr = lane & 3;     // mma thread-in-group
    const int g  = lane >> 3;    // dp4a row interleave 0..3
    const int j  = lane & 7;     // dp4a col interleave 0..7

    int macc[NI_MMA][4];
    #pragma unroll
    for (int ni = 0; ni < NI_MMA; ni++)
        #pragma unroll
        for (int r = 0; r < 4; r++) macc[ni][r] = 0;

    int dacc[4][NI_DP];
    #pragma unroll
    for (int mi = 0; mi < 4; mi++)
        #pragma unroll
        for (int ni = 0; ni < NI_DP; ni++) dacc[mi][ni] = 0;

    #pragma unroll
    for (int ks = 0; ks < 4; ks++) {
        // --- IMMA: cols 0..31 ---
        uint32_t af[4];
        {
            const uint32_t* p = &As[(rb + lq) * ROWSTRIDE + ks * 8 + lr];
            af[0] = p[0];  af[2] = p[4];
            const uint32_t* p8 = p + 8 * ROWSTRIDE;
            af[1] = p8[0]; af[3] = p8[4];
        }
        #pragma unroll
        for (int ni = 0; ni < NI_MMA; ni++) {
            const uint32_t* q = &Bs[(ni * 8 + lq) * ROWSTRIDE + ks * 8 + lr];
            uint32_t b0 = q[0], b1 = q[4];
            asm volatile(
                "mma.sync.aligned.m16n8k32.row.col.s32.s8.s8.s32 "
                "{%0,%1,%2,%3}, {%4,%5,%6,%7}, {%8,%9}, {%0,%1,%2,%3};"
                : "+r"(macc[ni][0]), "+r"(macc[ni][1]),
                  "+r"(macc[ni][2]), "+r"(macc[ni][3])
                : "r"(af[0]), "r"(af[1]), "r"(af[2]), "r"(af[3]),
                  "r"(b0), "r"(b1));
        }
        // --- dp4a: cols 32..63 ---
        #pragma unroll
        for (int c = 0; c < 2; c++) {
            const int kw = ks * 8 + c * 4;
            uint4 av[4];
            #pragma unroll
            for (int mi = 0; mi < 4; mi++)
                av[mi] = *(const uint4*)&As[(rb + g + 4 * mi) * ROWSTRIDE + kw];
            #pragma unroll
            for (int ni = 0; ni < NI_DP; ni++) {
                uint4 bv = *(const uint4*)&Bs[(COL_DP + j + 8 * ni) * ROWSTRIDE + kw];
                #pragma unroll
                for (int mi = 0; mi < 4; mi++) {
                    int v = dacc[mi][ni];
                    v = __dp4a((int)av[mi].x, (int)bv.x, v);
                    v = __dp4a((int)av[mi].y, (int)bv.y, v);
                    v = __dp4a((int)av[mi].z, (int)bv.z, v);
                    v = __dp4a((int)av[mi].w, (int)bv.w, v);
                    dacc[mi][ni] = v;
                }
            }
        }
    }

    // ---- Epilogue: round(alpha * acc) through fp16, store as f32 ----
    const float alpha = *alpha_p;
    float* obase = Out + ((size_t)bz * MDIM + (size_t)bm * BM) * NDIM + (size_t)bn * BN;

    #pragma unroll
    for (int ni = 0; ni < NI_MMA; ni++) {
        int c0 = ni * 8 + lr * 2;
        float2 v0;
        v0.x = __half2float(__float2half_rn(alpha * (float)macc[ni][0]));
        v0.y = __half2float(__float2half_rn(alpha * (float)macc[ni][1]));
        *(float2*)(obase + (size_t)(rb + lq) * NDIM + c0) = v0;
        float2 v1;
        v1.x = __half2float(__float2half_rn(alpha * (float)macc[ni][2]));
        v1.y = __half2float(__float2half_rn(alpha * (float)macc[ni][3]));
        *(float2*)(obase + (size_t)(rb + lq + 8) * NDIM + c0) = v1;
    }
    #pragma unroll
    for (int mi = 0; mi < 4; mi++) {
        float* orow = obase + (size_t)(rb + g + 4 * mi) * NDIM;
        #pragma unroll
        for (int ni = 0; ni < NI_DP; ni++) {
            int col = COL_DP + j + 8 * ni;
            orow[col] = __half2float(__float2half_rn(alpha * (float)dacc[mi][ni]));
        }
    }
}

extern "C" void kernel_launch(void* const* d_in, const int* in_sizes, int n_in,
                              void* d_out, int out_size) {
    // alpha is the size-1 input; the two large tensors are a then b in index order.
    int ai = -1, bi = -1, si = -1;
    for (int i = 0; i < n_in; i++) {
        if (in_sizes[i] == 1) { si = i; }
        else if (ai < 0)      { ai = i; }
        else                  { bi = i; }
    }
    const int*   a     = (const int*)d_in[ai];
    const int*   b     = (const int*)d_in[bi];
    const float* alpha = (const float*)d_in[si];
    float*       out   = (float*)d_out;

    // Phase 1: pack int32 -> int8 (8.39M values / 16 per thread / 256 = 2048 CTAs)
    pack_kernel<<<2048, 256>>>(a, b);

    // Phase 2: GEMM on packed data
    dim3 grid(NDIM / BN, MDIM / BM, BATCH);   // (16, 8, 64) = 8192 CTAs
    bmm_s8_main_kernel<<<grid, 256>>>(alpha, out);
}

// round 13
// speedup vs baseline: 1.3481x; 1.0193x over previous
#include <cuda_runtime.h>
#include <cuda_fp16.h>
#include <cstdint>

// BMM_S8T_S8N_F16T two-phase:
//  1) pack kernel: int32 inputs -> int8 packed scratch (static __device__)
//  2) main kernel: occ-3 hybrid, CTA tile 128x64; per 16-row warp slab:
//     IMMA cols 0..39 (ldmatrix fragment loads), dp4a cols 40..63.
// out[b,m,n] = f32( fp16_round( alpha * sum_k a[b,m,k]*b[b,n,k] ) )

#define BATCH 64
#define MDIM 1024
#define NDIM 1024
#define KDIM 128

#define BM 128
#define BN 64
#define ROWSTRIDE 36       // 32 k-words + 4 pad -> conflict-free banks

#define NI_MMA 5           // IMMA cols 0..39
#define COL_DP 40          // dp4a cols 40..63
#define NI_DP 3

__device__ uint4 g_Apack[(size_t)BATCH * MDIM * 8];
__device__ uint4 g_Bpack[(size_t)BATCH * NDIM * 8];

#define PACK4(v) __byte_perm(__byte_perm((v).x, (v).y, 0x0040), \
                             __byte_perm((v).z, (v).w, 0x0040), 0x5410)

static __device__ __forceinline__ uint32_t smem_u32(const void* p) {
    return (uint32_t)__cvta_generic_to_shared(p);
}

// ---------------- Pre-pass: pack int32 -> int8 ----------------
__global__ __launch_bounds__(256)
void pack_kernel(const int* __restrict__ A, const int* __restrict__ Bmat) {
    const int idx = blockIdx.x * 256 + threadIdx.x;
    const size_t base = (size_t)idx * 16;

    uint4 pa;
    {
        int4 v0 = *(const int4*)(A + base);
        int4 v1 = *(const int4*)(A + base + 4);
        int4 v2 = *(const int4*)(A + base + 8);
        int4 v3 = *(const int4*)(A + base + 12);
        pa.x = PACK4(v0); pa.y = PACK4(v1); pa.z = PACK4(v2); pa.w = PACK4(v3);
    }
    g_Apack[idx] = pa;

    uint4 pb;
    {
        int4 v0 = *(const int4*)(Bmat + base);
        int4 v1 = *(const int4*)(Bmat + base + 4);
        int4 v2 = *(const int4*)(Bmat + base + 8);
        int4 v3 = *(const int4*)(Bmat + base + 12);
        pb.x = PACK4(v0); pb.y = PACK4(v1); pb.z = PACK4(v2); pb.w = PACK4(v3);
    }
    g_Bpack[idx] = pb;
}

// ---------------- Main kernel ----------------
__global__ __launch_bounds__(256, 3)
void bmm_s8_main_kernel(const float* __restrict__ alpha_p,
                        float* __restrict__ Out) {
    __shared__ uint32_t As[BM * ROWSTRIDE];   // 18 KB
    __shared__ uint32_t Bs[BN * ROWSTRIDE];   //  9 KB

    const int tid  = threadIdx.x;
    const int lane = tid & 31;
    const int wid  = tid >> 5;

    const int bn = blockIdx.x;   // N block (16)
    const int bm = blockIdx.y;   // M block (8)
    const int bz = blockIdx.z;   // batch  (64)

    // ---- Load packed tiles ----
    {
        const uint4* Ab = g_Apack + ((size_t)bz * MDIM + bm * BM) * 8;
        #pragma unroll
        for (int i = 0; i < 4; i++) {
            int idx = tid + i * 256;
            int row = idx >> 3, qg = idx & 7;
            uint4 v = Ab[row * 8 + qg];
            *(uint4*)&As[row * ROWSTRIDE + qg * 4] = v;
        }
        const uint4* Bb = g_Bpack + ((size_t)bz * NDIM + bn * BN) * 8;
        #pragma unroll
        for (int i = 0; i < 2; i++) {
            int idx = tid + i * 256;
            int row = idx >> 3, qg = idx & 7;
            uint4 v = Bb[row * 8 + qg];
            *(uint4*)&Bs[row * ROWSTRIDE + qg * 4] = v;
        }
    }
    __syncthreads();

    const int rb = wid * 16;
    const int lr = lane & 3;     // mma thread-in-group
    const int lq = lane >> 2;    // mma group id
    const int g  = lane >> 3;    // dp4a row interleave 0..3
    const int j  = lane & 7;     // dp4a col interleave 0..7

    // ---- ldmatrix lane addresses ----
    // A x4: m0 rows 0-7 k-lo, m1 rows 8-15 k-lo, m2 rows 0-7 k-hi, m3 rows 8-15 k-hi
    const uint32_t a_lm = smem_u32(&As[(rb + (lane & 15)) * ROWSTRIDE
                                       + ((lane & 16) ? 4 : 0)]);
    // B x4 (ni pair p): m0 rows p16+0-7 k-lo, m1 same k-hi, m2 rows +8 k-lo, m3 +8 k-hi
    const uint32_t b_lmP = smem_u32(&Bs[((lane & 7) + ((lane & 16) ? 8 : 0)) * ROWSTRIDE
                                        + ((lane & 8) ? 4 : 0)]);
    // B x2 (ni 4): m0 rows 32+0-7 k-lo (lanes 0-7), m1 same rows k-hi (lanes 8-15)
    const uint32_t b_lm2 = smem_u32(&Bs[(32 + (lane & 7)) * ROWSTRIDE
                                        + ((lane & 8) ? 4 : 0)]);

    int macc[NI_MMA][4];
    #pragma unroll
    for (int ni = 0; ni < NI_MMA; ni++)
        #pragma unroll
        for (int r = 0; r < 4; r++) macc[ni][r] = 0;

    int dacc[4][NI_DP];
    #pragma unroll
    for (int mi = 0; mi < 4; mi++)
        #pragma unroll
        for (int ni = 0; ni < NI_DP; ni++) dacc[mi][ni] = 0;

    #pragma unroll
    for (int ks = 0; ks < 4; ks++) {
        // --- IMMA: cols 0..39, fragments via ldmatrix ---
        uint32_t af[4];
        asm volatile("ldmatrix.sync.aligned.m8n8.x4.shared.b16 {%0,%1,%2,%3}, [%4];"
                     : "=r"(af[0]), "=r"(af[1]), "=r"(af[2]), "=r"(af[3])
                     : "r"(a_lm + ks * 32));
        #pragma unroll
        for (int p = 0; p < 2; p++) {
            uint32_t bf[4];
            asm volatile("ldmatrix.sync.aligned.m8n8.x4.shared.b16 {%0,%1,%2,%3}, [%4];"
                         : "=r"(bf[0]), "=r"(bf[1]), "=r"(bf[2]), "=r"(bf[3])
                         : "r"(b_lmP + p * (16 * ROWSTRIDE * 4) + ks * 32));
            #pragma unroll
            for (int h = 0; h < 2; h++) {
                int ni = p * 2 + h;
                asm volatile(
                    "mma.sync.aligned.m16n8k32.row.col.s32.s8.s8.s32 "
                    "{%0,%1,%2,%3}, {%4,%5,%6,%7}, {%8,%9}, {%0,%1,%2,%3};"
                    : "+r"(macc[ni][0]), "+r"(macc[ni][1]),
                      "+r"(macc[ni][2]), "+r"(macc[ni][3])
                    : "r"(af[0]), "r"(af[1]), "r"(af[2]), "r"(af[3]),
                      "r"(bf[h * 2]), "r"(bf[h * 2 + 1]));
            }
        }
        {
            uint32_t bf[2];
            asm volatile("ldmatrix.sync.aligned.m8n8.x2.shared.b16 {%0,%1}, [%2];"
                         : "=r"(bf[0]), "=r"(bf[1])
                         : "r"(b_lm2 + ks * 32));
            asm volatile(
                "mma.sync.aligned.m16n8k32.row.col.s32.s8.s8.s32 "
                "{%0,%1,%2,%3}, {%4,%5,%6,%7}, {%8,%9}, {%0,%1,%2,%3};"
                : "+r"(macc[4][0]), "+r"(macc[4][1]),
                  "+r"(macc[4][2]), "+r"(macc[4][3])
                : "r"(af[0]), "r"(af[1]), "r"(af[2]), "r"(af[3]),
                  "r"(bf[0]), "r"(bf[1]));
        }

        // --- dp4a: cols 40..63 ---
        #pragma unroll
        for (int c = 0; c < 2; c++) {
            const int kw = ks * 8 + c * 4;
            uint4 av[4];
            #pragma unroll
            for (int mi = 0; mi < 4; mi++)
                av[mi] = *(const uint4*)&As[(rb + g + 4 * mi) * ROWSTRIDE + kw];
            #pragma unroll
            for (int ni = 0; ni < NI_DP; ni++) {
                uint4 bv = *(const uint4*)&Bs[(COL_DP + j + 8 * ni) * ROWSTRIDE + kw];
                #pragma unroll
                for (int mi = 0; mi < 4; mi++) {
                    int v = dacc[mi][ni];
                    v = __dp4a((int)av[mi].x, (int)bv.x, v);
                    v = __dp4a((int)av[mi].y, (int)bv.y, v);
                    v = __dp4a((int)av[mi].z, (int)bv.z, v);
                    v = __dp4a((int)av[mi].w, (int)bv.w, v);
                    dacc[mi][ni] = v;
                }
            }
        }
    }

    // ---- Epilogue ----
    const float alpha = *alpha_p;
    float* obase = Out + ((size_t)bz * MDIM + (size_t)bm * BM) * NDIM + (size_t)bn * BN;

    #pragma unroll
    for (int ni = 0; ni < NI_MMA; ni++) {
        int c0 = ni * 8 + lr * 2;
        float2 v0;
        v0.x = __half2float(__float2half_rn(alpha * (float)macc[ni][0]));
        v0.y = __half2float(__float2half_rn(alpha * (float)macc[ni][1]));
        *(float2*)(obase + (size_t)(rb + lq) * NDIM + c0) = v0;
        float2 v1;
        v1.x = __half2float(__float2half_rn(alpha * (float)macc[ni][2]));
        v1.y = __half2float(__float2half_rn(alpha * (float)macc[ni][3]));
        *(float2*)(obase + (size_t)(rb + lq + 8) * NDIM + c0) = v1;
    }
    #pragma unroll
    for (int mi = 0; mi < 4; mi++) {
        float* orow = obase + (size_t)(rb + g + 4 * mi) * NDIM;
        #pragma unroll
        for (int ni = 0; ni < NI_DP; ni++) {
            int col = COL_DP + j + 8 * ni;
            orow[col] = __half2float(__float2half_rn(alpha * (float)dacc[mi][ni]));
        }
    }
}

extern "C" void kernel_launch(void* const* d_in, const int* in_sizes, int n_in,
                              void* d_out, int out_size) {
    // alpha is the size-1 input; the two large tensors are a then b in index order.
    int ai = -1, bi = -1, si = -1;
    for (int i = 0; i < n_in; i++) {
        if (in_sizes[i] == 1) { si = i; }
        else if (ai < 0)      { ai = i; }
        else                  { bi = i; }
    }
    const int*   a     = (const int*)d_in[ai];
    const int*   b     = (const int*)d_in[bi];
    const float* alpha = (const float*)d_in[si];
    float*       out   = (float*)d_out;

    pack_kernel<<<2048, 256>>>(a, b);

    dim3 grid(NDIM / BN, MDIM / BM, BATCH);   // (16, 8, 64)
    bmm_s8_main_kernel<<<grid, 256>>>(alpha, out);
}